// round 16
// baseline (speedup 1.0000x reference)
#include <cuda_runtime.h>
#include <cstdint>

#define T_STEPS 50
#define BATCH   128
#define NIN     16384
#define NH      256
#define NO      11
#define M_TOT   (T_STEPS * BATCH)     // 6400

#define BM      64
#define BN      128
#define CHUNKS  (NIN / 32)            // 512
#define KSPLIT  6
#define CPK     86                    // 86*5 + 82 = 512
#define EPS     6e-3f

#define PLW     ((size_t)NH * NIN)

// ---------------------------------------------------------------------------
// Device scratch
// ---------------------------------------------------------------------------
__device__ float g_part[(size_t)KSPLIT * M_TOT * NH];
__device__ float g_cur1[(size_t)M_TOT * NH];
__device__ float g_spk1[(size_t)M_TOT * NH];
__device__ float g_cur2[(size_t)M_TOT * NO];
__device__ char  g_wq[2 * PLW];       // 2 int8 planes of W1
__device__ int   g_flags[1 + BATCH * NH];

__device__ __forceinline__ uint32_t pack4(int b0, int b1, int b2, int b3) {
    return (uint32_t)(b0 & 0xFF) | ((uint32_t)(b1 & 0xFF) << 8) |
           ((uint32_t)(b2 & 0xFF) << 16) | ((uint32_t)(b3 & 0xFF) << 24);
}

// ---------------------------------------------------------------------------
// Kernel 0: W1 -> 2 s8 planes. w ~= (w1*2^7 + w2) * 2^-18, |dw| <= 2^-19.
// ---------------------------------------------------------------------------
__global__ __launch_bounds__(256) void convw(const float* __restrict__ W1,
                                             char* __restrict__ wq) {
    const size_t gi = (size_t)blockIdx.x * 256 + threadIdx.x;
    float4 f = reinterpret_cast<const float4*>(W1)[gi];
    int p1[4], p2[4];
    const float* fv = &f.x;
#pragma unroll
    for (int i = 0; i < 4; i++) {
        int wi = __float2int_rn(fv[i] * 262144.0f);     // w * 2^18
        wi = max(-16255, min(16255, wi));
        p1[i] = (wi + 64) >> 7;
        p2[i] = wi - (p1[i] << 7);
    }
    reinterpret_cast<uint32_t*>(wq)[gi]       = pack4(p1[0], p1[1], p1[2], p1[3]);
    reinterpret_cast<uint32_t*>(wq + PLW)[gi] = pack4(p2[0], p2[1], p2[2], p2[3]);
}

// ---------------------------------------------------------------------------
// Kernel 1: partial[ks] = approx X @ W1^T via dp4a, 3 product groups.
// X quantized inline (x ~= (x1*2^7 + x2)*2^-11). Tile 64x128, 256 threads
// (8 warps 2Mx4N), thread tile 8x4, single-buffer reg-prefetch (R1 pattern).
// grid (2, 100, 6).
// ---------------------------------------------------------------------------
__global__ __launch_bounds__(256) void gemm_dp4a(
    const float* __restrict__ X,
    const char* __restrict__ wq,
    float* __restrict__ part)
{
    __shared__ uint32_t Xs1[512], Xs2[512];        // [quad][row] 8x64
    __shared__ uint32_t Ws1[1024], Ws2[1024];      // [quad][col] 8x128

    const int tid  = threadIdx.x;
    const int wid  = tid >> 5;
    const int lane = tid & 31;
    const int n0 = blockIdx.x * BN;
    const int m0 = blockIdx.y * BM;
    const int c0 = blockIdx.z * CPK;
    const int nch = min(CHUNKS - c0, CPK);
    const int warpM = wid & 1;
    const int warpN = wid >> 1;
    const int lm = lane >> 3;          // 0..3
    const int ln = lane & 7;           // 0..7
    const int r0 = warpM * 32 + lm * 8;
    const int cb = warpN * 32 + ln * 4;

    // X producer: thread -> row tid>>2, k-offset (tid&3)*8
    const int xrow = tid >> 2;
    const int xko  = (tid & 3) * 8;    // 0,8,16,24
    const float* xp = X + (size_t)(m0 + xrow) * NIN + (size_t)c0 * 32 + xko;
    const int xq0 = xko >> 2;          // first quad written (0,2,4,6)

    // W producer: thread -> plane tid>>7, row tid&127, 8 u32 (32B)
    const int wpl = tid >> 7;
    const int wrow = tid & 127;
    const char* wp = wq + (size_t)wpl * PLW + (size_t)(n0 + wrow) * NIN
                   + (size_t)c0 * 32;
    uint32_t* WsP = wpl ? Ws2 : Ws1;

    int acc1[8][4], acc2[8][4];
#pragma unroll
    for (int i = 0; i < 8; i++)
#pragma unroll
        for (int j = 0; j < 4; j++) { acc1[i][j] = 0; acc2[i][j] = 0; }

    // prefetch chunk 0
    float4 xa = *reinterpret_cast<const float4*>(xp);
    float4 xb = *reinterpret_cast<const float4*>(xp + 4);
    int4 wa = *reinterpret_cast<const int4*>(wp);
    int4 wb = *reinterpret_cast<const int4*>(wp + 16);

    for (int c = 0; c < nch; c++) {
        __syncthreads();               // previous compute done

        // quantize + stage X(c)
        {
            int h[8], l[8];
            const float* fa = &xa.x;
            const float* fb = &xb.x;
#pragma unroll
            for (int i = 0; i < 8; i++) {
                float v = (i < 4) ? fa[i] : fb[i - 4];
                int xi = __float2int_rn(v * 2048.0f);   // x * 2^11
                xi = max(-16255, min(16255, xi));
                h[i] = (xi + 64) >> 7;
                l[i] = xi - (h[i] << 7);
            }
            Xs1[(xq0 + 0) * 64 + xrow] = pack4(h[0], h[1], h[2], h[3]);
            Xs1[(xq0 + 1) * 64 + xrow] = pack4(h[4], h[5], h[6], h[7]);
            Xs2[(xq0 + 0) * 64 + xrow] = pack4(l[0], l[1], l[2], l[3]);
            Xs2[(xq0 + 1) * 64 + xrow] = pack4(l[4], l[5], l[6], l[7]);
        }
        // stage W(c): 8 u32 -> [quad][col]
        {
            const uint32_t* wv = reinterpret_cast<const uint32_t*>(&wa);
#pragma unroll
            for (int q = 0; q < 4; q++) WsP[q * 128 + wrow] = wv[q];
            const uint32_t* wv2 = reinterpret_cast<const uint32_t*>(&wb);
#pragma unroll
            for (int q = 0; q < 4; q++) WsP[(q + 4) * 128 + wrow] = wv2[q];
        }

        // prefetch chunk c+1
        if (c + 1 < nch) {
            const float* xn = xp + (size_t)(c + 1) * 32;
            const char*  wn = wp + (size_t)(c + 1) * 32;
            xa = *reinterpret_cast<const float4*>(xn);
            xb = *reinterpret_cast<const float4*>(xn + 4);
            wa = *reinterpret_cast<const int4*>(wn);
            wb = *reinterpret_cast<const int4*>(wn + 16);
        }

        __syncthreads();               // tiles visible

        // compute: 8 k-quads x (8m x 4n) x 3 groups
#pragma unroll
        for (int q = 0; q < 8; q++) {
            uint4 A1a = *reinterpret_cast<const uint4*>(&Xs1[q * 64 + r0]);
            uint4 A1b = *reinterpret_cast<const uint4*>(&Xs1[q * 64 + r0 + 4]);
            uint4 A2a = *reinterpret_cast<const uint4*>(&Xs2[q * 64 + r0]);
            uint4 A2b = *reinterpret_cast<const uint4*>(&Xs2[q * 64 + r0 + 4]);
            uint4 B1v = *reinterpret_cast<const uint4*>(&Ws1[q * 128 + cb]);
            uint4 B2v = *reinterpret_cast<const uint4*>(&Ws2[q * 128 + cb]);
            uint32_t a1[8] = {A1a.x, A1a.y, A1a.z, A1a.w,
                              A1b.x, A1b.y, A1b.z, A1b.w};
            uint32_t a2[8] = {A2a.x, A2a.y, A2a.z, A2a.w,
                              A2b.x, A2b.y, A2b.z, A2b.w};
            uint32_t b1[4] = {B1v.x, B1v.y, B1v.z, B1v.w};
            uint32_t b2[4] = {B2v.x, B2v.y, B2v.z, B2v.w};
#pragma unroll
            for (int i = 0; i < 8; i++)
#pragma unroll
                for (int j = 0; j < 4; j++) {
                    acc1[i][j] = __dp4a((int)a1[i], (int)b1[j], acc1[i][j]);
                    acc2[i][j] = __dp4a((int)a1[i], (int)b2[j], acc2[i][j]);
                    acc2[i][j] = __dp4a((int)a2[i], (int)b1[j], acc2[i][j]);
                }
        }
    }

    // epilogue: cur = acc1*2^-15 + acc2*2^-22, raw partial store
    float* po = part + (size_t)blockIdx.z * M_TOT * NH;
#pragma unroll
    for (int i = 0; i < 8; i++) {
        const int row = m0 + r0 + i;
        float4 v;
        v.x = fmaf((float)acc2[i][0], 0x1p-22f, (float)acc1[i][0] * 0x1p-15f);
        v.y = fmaf((float)acc2[i][1], 0x1p-22f, (float)acc1[i][1] * 0x1p-15f);
        v.z = fmaf((float)acc2[i][2], 0x1p-22f, (float)acc1[i][2] * 0x1p-15f);
        v.w = fmaf((float)acc2[i][3], 0x1p-22f, (float)acc1[i][3] * 0x1p-15f);
        *reinterpret_cast<float4*>(po + (size_t)row * NH + n0 + cb) = v;
    }
}

// ---------------------------------------------------------------------------
// Kernel 2: reduce 6 partials + bias -> cur1; flag near-threshold chains.
// ---------------------------------------------------------------------------
__global__ __launch_bounds__(256) void reduce_flag(
    const float* __restrict__ part,
    const float* __restrict__ b1,
    float* __restrict__ cur1,
    int* __restrict__ flags)
{
    const int b = blockIdx.x, j = threadIdx.x;
    const float bias = b1[j];
    const size_t P = (size_t)M_TOT * NH;
    const size_t base = (size_t)b * NH + j;
    const size_t ts = (size_t)BATCH * NH;

    float mem = 0.0f;
    bool risky = false;
#pragma unroll 5
    for (int t = 0; t < T_STEPS; t++) {
        const size_t idx = base + (size_t)t * ts;
        float c = (((part[idx] + part[idx + P])
                  + (part[idx + 2 * P] + part[idx + 3 * P]))
                  + (part[idx + 4 * P] + part[idx + 5 * P])) + bias;
        cur1[idx] = c;
        mem = 0.9f * mem + c;
        const float d = mem - 1.0f;
        risky |= (fabsf(d) < EPS);
        mem -= (d > 0.0f) ? 1.0f : 0.0f;
    }
    if (risky) {
        const int pos = atomicAdd(&flags[0], 1);
        flags[1 + pos] = (b << 8) | j;
    }
}

// ---------------------------------------------------------------------------
// Kernel 3: bitwise-R1 repair of flagged chains (proven in R12/13/15).
// ---------------------------------------------------------------------------
__global__ __launch_bounds__(256) void fix2(
    const float* __restrict__ X,
    const float* __restrict__ W1,
    const float* __restrict__ b1,
    float* __restrict__ cur1,
    const int* __restrict__ flags)
{
    const int total = flags[0] * T_STEPS;
    for (int idx = blockIdx.x * blockDim.x + threadIdx.x; idx < total;
         idx += gridDim.x * blockDim.x) {
        const int ci = idx / T_STEPS;
        const int t  = idx - ci * T_STEPS;
        const int bj = flags[1 + ci];
        const int b = bj >> 8, j = bj & (NH - 1);
        const float* xr = X + ((size_t)t * BATCH + b) * NIN;
        const float* wr = W1 + (size_t)j * NIN;
        float acc = 0.0f;
        for (int k = 0; k < NIN; k += 8) {
            float4 x0 = *reinterpret_cast<const float4*>(xr + k);
            float4 x1 = *reinterpret_cast<const float4*>(xr + k + 4);
            float4 w0 = *reinterpret_cast<const float4*>(wr + k);
            float4 w1 = *reinterpret_cast<const float4*>(wr + k + 4);
            acc = fmaf(x0.x, w0.x, acc);
            acc = fmaf(x0.y, w0.y, acc);
            acc = fmaf(x0.z, w0.z, acc);
            acc = fmaf(x0.w, w0.w, acc);
            acc = fmaf(x1.x, w1.x, acc);
            acc = fmaf(x1.y, w1.y, acc);
            acc = fmaf(x1.z, w1.z, acc);
            acc = fmaf(x1.w, w1.w, acc);
        }
        cur1[((size_t)t * BATCH + b) * NH + j] = acc + b1[j];
    }
}

// ---------------------------------------------------------------------------
// Kernels 4-6: VERBATIM round-14 split scan path (proven bitwise).
// ---------------------------------------------------------------------------
__global__ __launch_bounds__(256) void scan1(const float* __restrict__ cur1,
                                             float* __restrict__ spk1) {
    const int b = blockIdx.x, j = threadIdx.x;
    float mem1 = 0.0f;
#pragma unroll 5
    for (int t = 0; t < T_STEPS; t++) {
        const float c1 = cur1[((size_t)t * BATCH + b) * NH + j];
        mem1 = 0.9f * mem1 + c1;
        const float spk = (mem1 - 1.0f > 0.0f) ? 1.0f : 0.0f;
        mem1 -= spk;
        spk1[((size_t)t * BATCH + b) * NH + j] = spk;
    }
}

__global__ __launch_bounds__(256) void layer2k(const float* __restrict__ spk1,
                                               const float* __restrict__ W2,
                                               const float* __restrict__ b2,
                                               float* __restrict__ cur2) {
    const int w8  = threadIdx.x >> 5;
    const int lid = threadIdx.x & 31;
    const int tb  = blockIdx.x * 8 + w8;

    float acc[NO];
#pragma unroll
    for (int o = 0; o < NO; o++) acc[o] = b2[o];

    const float* srow = spk1 + (size_t)tb * NH;

#pragma unroll
    for (int w = 0; w < 8; w++) {
        const float s = srow[w * 32 + lid];
        float p[NO];
#pragma unroll
        for (int o = 0; o < NO; o++) p[o] = s * W2[o * NH + w * 32 + lid];
#pragma unroll
        for (int o = 0; o < NO; o++) {
#pragma unroll
            for (int off = 16; off > 0; off >>= 1)
                p[o] += __shfl_xor_sync(0xFFFFFFFFu, p[o], off);
        }
#pragma unroll
        for (int o = 0; o < NO; o++) {
            const float q0 = __shfl_sync(0xFFFFFFFFu, p[o], 0);
            acc[o] += q0;
        }
    }

    if (lid < NO)
        cur2[(size_t)tb * NO + lid] = acc[lid];
}

__global__ __launch_bounds__(256) void scan2(const float* __restrict__ cur2,
                                             float* __restrict__ out) {
    const int gid = blockIdx.x * 256 + threadIdx.x;
    if (gid >= BATCH * NO) return;
    float mem2 = 0.0f;
#pragma unroll 5
    for (int t = 0; t < T_STEPS; t++) {
        const float c2 = cur2[(size_t)t * BATCH * NO + gid];
        mem2 = 0.9f * mem2 + c2;
        const float spk = (mem2 - 1.0f > 0.0f) ? 1.0f : 0.0f;
        mem2 -= spk;
        out[(size_t)t * BATCH * NO + gid] = spk;
    }
}

// ---------------------------------------------------------------------------
extern "C" void kernel_launch(void* const* d_in, const int* in_sizes, int n_in,
                              void* d_out, int out_size)
{
    const float* x  = (const float*)d_in[0];
    const float* W1 = (const float*)d_in[1];
    const float* b1 = (const float*)d_in[2];
    const float* W2 = (const float*)d_in[3];
    const float* b2 = (const float*)d_in[4];
    float* out = (float*)d_out;

    float *partp, *cur1, *spk1, *cur2;
    char* wqp;
    int* flagsp;
    cudaGetSymbolAddress((void**)&partp, g_part);
    cudaGetSymbolAddress((void**)&cur1, g_cur1);
    cudaGetSymbolAddress((void**)&spk1, g_spk1);
    cudaGetSymbolAddress((void**)&cur2, g_cur2);
    cudaGetSymbolAddress((void**)&wqp, g_wq);
    cudaGetSymbolAddress((void**)&flagsp, g_flags);

    cudaMemsetAsync(flagsp, 0, sizeof(int));
    convw<<<(int)(PLW / 4 / 256), 256>>>(W1, wqp);
    gemm_dp4a<<<dim3(2, 100, KSPLIT), 256>>>(x, wqp, partp);
    reduce_flag<<<BATCH, NH>>>(partp, b1, cur1, flagsp);
    fix2<<<592, 256>>>(x, W1, b1, cur1, flagsp);
    scan1<<<BATCH, NH>>>(cur1, spk1);
    layer2k<<<M_TOT / 8, 256>>>(spk1, W2, b2, cur2);
    scan2<<<(BATCH * NO + 255) / 256, 256>>>(cur2, out);
}